// round 3
// baseline (speedup 1.0000x reference)
#include <cuda_runtime.h>
#include <cstdint>

#define BB    16
#define HH    320
#define WW    1024
#define HWW   (HH * WW)          // 327680
#define NN    16384
#define NWORDS (HWW / 32)        // 10240
#define MAXD  40.0f

#define NBUK1 16384              // round-1 buckets: key1 >> 18
#define NBUK2 4096               // round-2 buckets: key2 >> 17 (keys < 2^29)
#define KEY2_T (1u << 29)        // prefix filter threshold (~1/8 -> ~41K survivors)
#define CAP2  65536              // appended-survivor capacity
#define BCAP  128                // per-bucket SMEM cap

// ---------------- device scratch ----------------
__device__ unsigned long long g_c1[HWW];      // composite1 = key1<<19 | i  (linear)
__device__ unsigned long long g_buf1[HWW];    // bucketed composite1
__device__ uint32_t g_A1[HWW];                // round-1 argsort result (pixel ids)
__device__ unsigned long long g_app[CAP2];    // filtered composite2 (unordered)
__device__ unsigned long long g_buf2[CAP2];   // bucketed composite2
__device__ uint32_t g_permPre[CAP2];          // final perm prefix (shared across batches)
__device__ int g_hist1[NBUK1], g_bstart1[NBUK1 + 1], g_cur1[NBUK1];
__device__ int g_hist2[NBUK2], g_bstart2[NBUK2 + 1], g_cur2[NBUK2];
__device__ int g_s2cnt;
__device__ uint32_t g_bm[BB * NWORDS];
__device__ int g_validNum[BB];
__device__ int g_validPix[BB * NN];

// ---------------- threefry2x32 (jax-exact) ----------------
__host__ __device__ __forceinline__ void tf2x32(uint32_t k0, uint32_t k1,
                                                uint32_t x0, uint32_t x1,
                                                uint32_t& o0, uint32_t& o1) {
    uint32_t ks0 = k0, ks1 = k1, ks2 = 0x1BD11BDAu ^ k0 ^ k1;
    x0 += ks0; x1 += ks1;
    #define TFMIX(r) { x0 += x1; x1 = (x1 << (r)) | (x1 >> (32 - (r))); x1 ^= x0; }
    TFMIX(13) TFMIX(15) TFMIX(26) TFMIX(6)  x0 += ks1; x1 += ks2 + 1u;
    TFMIX(17) TFMIX(29) TFMIX(16) TFMIX(24) x0 += ks2; x1 += ks0 + 2u;
    TFMIX(13) TFMIX(15) TFMIX(26) TFMIX(6)  x0 += ks0; x1 += ks1 + 3u;
    TFMIX(17) TFMIX(29) TFMIX(16) TFMIX(24) x0 += ks1; x1 += ks2 + 4u;
    TFMIX(13) TFMIX(15) TFMIX(26) TFMIX(6)  x0 += ks2; x1 += ks0 + 5u;
    #undef TFMIX
    o0 = x0; o1 = x1;
}

__device__ __forceinline__ uint32_t rbits(uint32_t k0, uint32_t k1, uint32_t i) {
    uint32_t a, b;
    tf2x32(k0, k1, 0u, i, a, b);
    return a ^ b;
}

// ---------------- K: zero counters ----------------
__global__ void k_zero() {
    int i = blockIdx.x * 256 + threadIdx.x;
    if (i < NBUK1) g_hist1[i] = 0;
    if (i < NBUK2) g_hist2[i] = 0;
    if (i < BB)    g_validNum[i] = 0;
    if (i == 0)    g_s2cnt = 0;
}

// ---------------- K: single pass computing both keys ----------------
__global__ void k_prep(uint32_t a0, uint32_t a1, uint32_t b0, uint32_t b1) {
    uint32_t i = blockIdx.x * 256 + threadIdx.x;
    uint32_t key1 = rbits(a0, a1, i);
    uint32_t key2 = rbits(b0, b1, i);
    g_c1[i] = ((unsigned long long)key1 << 19) | (unsigned long long)i;
    atomicAdd(&g_hist1[key1 >> 18], 1);
    if (key2 < KEY2_T) {
        atomicAdd(&g_hist2[key2 >> 17], 1);
        int pos = atomicAdd(&g_s2cnt, 1);
        if (pos < CAP2)
            g_app[pos] = ((unsigned long long)key2 << 19) | (unsigned long long)i;
    }
}

// ---------------- K: scan both histograms (2 CTAs) ----------------
__global__ void k_scan2() {
    __shared__ int part[1024];
    int t = threadIdx.x;
    if (blockIdx.x == 0) {
        int loc[16]; int s = 0;
#pragma unroll
        for (int i = 0; i < 16; i++) { loc[i] = s; s += g_hist1[t * 16 + i]; }
        part[t] = s;
        __syncthreads();
        for (int off = 1; off < 1024; off <<= 1) {
            int u = (t >= off) ? part[t - off] : 0;
            __syncthreads();
            part[t] += u;
            __syncthreads();
        }
        int excl = part[t] - s;
#pragma unroll
        for (int i = 0; i < 16; i++) {
            int v = excl + loc[i];
            g_bstart1[t * 16 + i] = v;
            g_cur1[t * 16 + i] = v;
        }
        if (t == 1023) g_bstart1[NBUK1] = part[1023];
    } else {
        int loc[4]; int s = 0;
#pragma unroll
        for (int i = 0; i < 4; i++) { loc[i] = s; s += g_hist2[t * 4 + i]; }
        part[t] = s;
        __syncthreads();
        for (int off = 1; off < 1024; off <<= 1) {
            int u = (t >= off) ? part[t - off] : 0;
            __syncthreads();
            part[t] += u;
            __syncthreads();
        }
        int excl = part[t] - s;
#pragma unroll
        for (int i = 0; i < 4; i++) {
            int v = excl + loc[i];
            g_bstart2[t * 4 + i] = v;
            g_cur2[t * 4 + i] = v;
        }
        if (t == 1023) g_bstart2[NBUK2] = part[1023];
    }
}

// ---------------- K: place round 1 (reads stored composites) ----------------
__global__ void k_place1() {
    uint32_t i = blockIdx.x * 256 + threadIdx.x;
    unsigned long long c = g_c1[i];
    int digit = (int)(c >> 37);          // key1 >> 18
    int pos = atomicAdd(&g_cur1[digit], 1);
    g_buf1[pos] = c;
}

// ---------------- K: in-bucket rank sort round 1 -> A1 ----------------
__global__ void k_bsort1() {
    __shared__ unsigned long long sb[8 * BCAP];
    int wid = threadIdx.x >> 5, lane = threadIdx.x & 31;
    int buk = blockIdx.x * 8 + wid;
    int start = g_bstart1[buk];
    int m = g_bstart1[buk + 1] - start;
    if (m <= BCAP) {
        for (int e = lane; e < m; e += 32) sb[wid * BCAP + e] = g_buf1[start + e];
        __syncwarp();
        for (int e = lane; e < m; e += 32) {
            unsigned long long ke = sb[wid * BCAP + e];
            int r = 0;
            for (int i = 0; i < m; i++) r += (sb[wid * BCAP + i] < ke) ? 1 : 0;
            g_A1[start + r] = (uint32_t)(ke & 0x7FFFFu);
        }
    } else {
        for (int e = lane; e < m; e += 32) {
            unsigned long long ke = g_buf1[start + e];
            int r = 0;
            for (int i = 0; i < m; i++) r += (g_buf1[start + i] < ke) ? 1 : 0;
            g_A1[start + r] = (uint32_t)(ke & 0x7FFFFu);
        }
    }
}

// ---------------- K: place round 2 (filtered survivors) ----------------
__global__ void k_place2() {
    int i = blockIdx.x * 256 + threadIdx.x;
    int SA = g_s2cnt; if (SA > CAP2) SA = CAP2;
    if (i >= SA) return;
    unsigned long long c = g_app[i];
    int digit = (int)(c >> 36);          // key2 >> 17
    int pos = atomicAdd(&g_cur2[digit], 1);
    g_buf2[pos] = c;
}

// ---------------- K: in-bucket rank sort round 2 + fused A1 gather ----------------
__global__ void k_bsort2() {
    __shared__ unsigned long long sb[8 * BCAP];
    int wid = threadIdx.x >> 5, lane = threadIdx.x & 31;
    int buk = blockIdx.x * 8 + wid;
    int start = g_bstart2[buk];
    int m = g_bstart2[buk + 1] - start;
    if (m <= BCAP) {
        for (int e = lane; e < m; e += 32) sb[wid * BCAP + e] = g_buf2[start + e];
        __syncwarp();
        for (int e = lane; e < m; e += 32) {
            unsigned long long ke = sb[wid * BCAP + e];
            int r = 0;
            for (int i = 0; i < m; i++) r += (sb[wid * BCAP + i] < ke) ? 1 : 0;
            g_permPre[start + r] = g_A1[(uint32_t)(ke & 0x7FFFFu)];
        }
    } else {
        for (int e = lane; e < m; e += 32) {
            unsigned long long ke = g_buf2[start + e];
            int r = 0;
            for (int i = 0; i < m; i++) r += (g_buf2[start + i] < ke) ? 1 : 0;
            g_permPre[start + r] = g_A1[(uint32_t)(ke & 0x7FFFFu)];
        }
    }
}

// ---------------- K: validity bitmask + fused valid_number ----------------
__global__ void k_bitmask(const float* __restrict__ depth) {
    __shared__ int sc;
    if (threadIdx.x == 0) sc = 0;
    __syncthreads();
    int b = blockIdx.y;
    int base = blockIdx.x * 2048;
    int lane = threadIdx.x & 31;
    const float* dp = depth + (size_t)b * HWW;
    int mycnt = 0;
#pragma unroll
    for (int it = 0; it < 8; it++) {
        int p = base + it * 256 + threadIdx.x;
        float d = dp[p];
        unsigned bal = __ballot_sync(0xffffffffu, d < MAXD);
        if (lane == 0) { g_bm[b * NWORDS + (p >> 5)] = bal; mycnt += __popc(bal); }
    }
    if (lane == 0) atomicAdd(&sc, mycnt);
    __syncthreads();
    if (threadIdx.x == 0) atomicAdd(&g_validNum[b], sc);
}

// ---------------- K: stable compaction of first NN valid pixels (1 CTA/batch) ----------------
__global__ void k_compact() {
    __shared__ uint32_t bm[NWORDS];     // 40 KB
    __shared__ int sW[32];
    __shared__ int sOff;
    int b = blockIdx.x;
    int tid = threadIdx.x;
    for (int i = tid; i < NWORDS; i += 1024) bm[i] = g_bm[b * NWORDS + i];
    if (tid == 0) sOff = 0;
    __syncthreads();
    int totS = g_bstart2[NBUK2]; if (totS > CAP2) totS = CAP2;
    int lane = tid & 31, wid = tid >> 5;
    unsigned lmask = (1u << lane) - 1u;
    for (int base = 0; base < CAP2; base += 1024) {
        int off = sOff;
        if (off >= NN || base >= totS) break;   // uniform across CTA
        int j = base + tid;
        bool valid = false;
        uint32_t p = 0;
        if (j < totS) {
            p = g_permPre[j];
            valid = (bm[p >> 5] >> (p & 31)) & 1u;
        }
        unsigned bal = __ballot_sync(0xffffffffu, valid);
        if (lane == 0) sW[wid] = __popc(bal);
        __syncthreads();
        int wp = 0, tot = 0;
#pragma unroll
        for (int w = 0; w < 32; w++) { int c = sW[w]; tot += c; wp += (w < wid) ? c : 0; }
        if (valid) {
            int g = off + wp + __popc(bal & lmask);
            if (g < NN) g_validPix[b * NN + g] = (int)p;
        }
        __syncthreads();
        if (tid == 0) sOff = off + tot;
        __syncthreads();
    }
}

// ---------------- K: epilogue ----------------
__global__ void k_output(const float* __restrict__ depth, const float* __restrict__ invK,
                         const float* __restrict__ bind, float* __restrict__ out) {
    int b = blockIdx.y;
    int n = blockIdx.x * 256 + threadIdx.x;
    float bv = bind[b * NN + n];
    float vnf = (float)g_validNum[b];
    int li = (vnf > 0.0f) ? (int)fmodf(bv, vnf) : 0;
    int p = g_validPix[b * NN + li];
    float d = __ldg(&depth[(size_t)b * HWW + p]);
    float xf = (float)(p & (WW - 1));
    float yf = (float)(p >> 10);
    float px = xf * d, py = yf * d;
    const float* Km = invK + b * 16;
#pragma unroll
    for (int c = 0; c < 3; c++) {
        float v = fmaf(__ldg(&Km[c * 4 + 0]), px,
                  fmaf(__ldg(&Km[c * 4 + 1]), py,
                  fmaf(__ldg(&Km[c * 4 + 2]), d, __ldg(&Km[c * 4 + 3]))));
        out[((size_t)b * 3 + c) * NN + n] = v;
    }
}

// ================================= launch =================================
extern "C" void kernel_launch(void* const* d_in, const int* in_sizes, int n_in,
                              void* d_out, int out_size) {
    const float* depth = (const float*)d_in[0];
    const float* invK  = (const float*)d_in[1];
    const float* bind  = (const float*)d_in[3];
    float* out = (float*)d_out;

    // jax key schedule: key(42) = (0,42); per shuffle round: key,subkey = split(key)
    uint32_t k0 = 0u, k1 = 42u;
    uint32_t sk[2][2];
    for (int r = 0; r < 2; r++) {
        uint32_t nk0, nk1, s0, s1;
        tf2x32(k0, k1, 0u, 0u, nk0, nk1);
        tf2x32(k0, k1, 0u, 1u, s0, s1);
        k0 = nk0; k1 = nk1;
        sk[r][0] = s0; sk[r][1] = s1;
    }

    k_zero   <<<(NBUK1 + 255) / 256, 256>>>();
    k_prep   <<<HWW / 256, 256>>>(sk[0][0], sk[0][1], sk[1][0], sk[1][1]);
    k_scan2  <<<2, 1024>>>();
    k_place1 <<<HWW / 256, 256>>>();
    k_bsort1 <<<NBUK1 / 8, 256>>>();
    k_place2 <<<CAP2 / 256, 256>>>();
    k_bsort2 <<<NBUK2 / 8, 256>>>();
    k_bitmask<<<dim3(160, BB), 256>>>(depth);
    k_compact<<<BB, 1024>>>();
    k_output <<<dim3(NN / 256, BB), 256>>>(depth, invK, bind, out);
}

// round 4
// speedup vs baseline: 1.2809x; 1.2809x over previous
#include <cuda_runtime.h>
#include <cstdint>

#define BB    16
#define HH    320
#define WW    1024
#define HWW   (HH * WW)          // 327680
#define NN    16384
#define NWORDS (HWW / 32)        // 10240
#define MAXD  40.0f

#define NBUK1 16384              // round-1 buckets: key1 >> 18 (mean load 20)
#define CAP1  64
#define NBUK2 4096               // round-2 buckets: key2 >> 17 (mean load ~10)
#define CAP2B 64
#define KEY2_T (1u << 29)        // survivor filter (~41K expected; need ~33K)
#define CAP2T 65536              // survivor-position space scanned by compact

// ---------------- device scratch ----------------
__device__ unsigned long long g_pad1[NBUK1 * CAP1];   // 8 MB padded round-1 buckets
__device__ unsigned long long g_pad2[NBUK2 * CAP2B];  // 2 MB padded round-2 buckets
__device__ int g_cnt1[NBUK1], g_cnt2[NBUK2];
__device__ int g_bstart1[NBUK1 + 1], g_bstart2[NBUK2 + 1];
__device__ uint32_t g_A1[HWW];              // full round-1 argsort (pixel ids)
__device__ uint32_t g_permPre[CAP2T];       // final perm prefix (batch-independent)
__device__ uint32_t g_bm[BB * NWORDS];
__device__ int g_validNum[BB];
__device__ int g_validPix[BB * NN];

// ---------------- threefry2x32 (jax-exact, partitionable mode) ----------------
__host__ __device__ __forceinline__ void tf2x32(uint32_t k0, uint32_t k1,
                                                uint32_t x0, uint32_t x1,
                                                uint32_t& o0, uint32_t& o1) {
    uint32_t ks0 = k0, ks1 = k1, ks2 = 0x1BD11BDAu ^ k0 ^ k1;
    x0 += ks0; x1 += ks1;
    #define TFMIX(r) { x0 += x1; x1 = (x1 << (r)) | (x1 >> (32 - (r))); x1 ^= x0; }
    TFMIX(13) TFMIX(15) TFMIX(26) TFMIX(6)  x0 += ks1; x1 += ks2 + 1u;
    TFMIX(17) TFMIX(29) TFMIX(16) TFMIX(24) x0 += ks2; x1 += ks0 + 2u;
    TFMIX(13) TFMIX(15) TFMIX(26) TFMIX(6)  x0 += ks0; x1 += ks1 + 3u;
    TFMIX(17) TFMIX(29) TFMIX(16) TFMIX(24) x0 += ks1; x1 += ks2 + 4u;
    TFMIX(13) TFMIX(15) TFMIX(26) TFMIX(6)  x0 += ks2; x1 += ks0 + 5u;
    #undef TFMIX
    o0 = x0; o1 = x1;
}

__device__ __forceinline__ uint32_t rbits(uint32_t k0, uint32_t k1, uint32_t i) {
    uint32_t a, b;
    tf2x32(k0, k1, 0u, i, a, b);
    return a ^ b;
}

// ---------------- K0: zero counters ----------------
__global__ void k_zero() {
    int i = blockIdx.x * 256 + threadIdx.x;
    if (i < NBUK1) g_cnt1[i] = 0;
    if (i < NBUK2) g_cnt2[i] = 0;
    if (i < BB)    g_validNum[i] = 0;
}

// ---------------- K1: fused keygen + histogram + padded placement ----------------
// 2 elements per thread for atomic-latency ILP.
__global__ void k_prep(uint32_t a0, uint32_t a1, uint32_t b0, uint32_t b1) {
    uint32_t base = blockIdx.x * 512 + threadIdx.x;
#pragma unroll
    for (int e = 0; e < 2; e++) {
        uint32_t i = base + e * 256;
        uint32_t key1 = rbits(a0, a1, i);
        uint32_t key2 = rbits(b0, b1, i);
        int b1i = key1 >> 18;
        int s1 = atomicAdd(&g_cnt1[b1i], 1);
        if (s1 < CAP1)
            g_pad1[b1i * CAP1 + s1] = ((unsigned long long)key1 << 19) | i;
        if (key2 < KEY2_T) {
            int b2i = key2 >> 17;
            int s2 = atomicAdd(&g_cnt2[b2i], 1);
            if (s2 < CAP2B)
                g_pad2[b2i * CAP2B + s2] = ((unsigned long long)key2 << 19) | i;
        }
    }
}

// ---------------- K2: exclusive scans of both counter arrays (2 CTAs) ----------------
__device__ __forceinline__ void scan_hist(const int* hist, int* bstart, int n, int E) {
    __shared__ int wsum[32];
    int t = threadIdx.x, lane = t & 31, wid = t >> 5;
    int loc[16]; int s = 0;
    for (int i = 0; i < E; i++) { loc[i] = s; s += hist[t * E + i]; }
    int inc = s;
    for (int o = 1; o < 32; o <<= 1) {
        int u = __shfl_up_sync(0xffffffffu, inc, o);
        if (lane >= o) inc += u;
    }
    if (lane == 31) wsum[wid] = inc;
    __syncthreads();
    if (wid == 0) {
        int v = wsum[lane];
        for (int o = 1; o < 32; o <<= 1) {
            int u = __shfl_up_sync(0xffffffffu, v, o);
            if (lane >= o) v += u;
        }
        wsum[lane] = v;
    }
    __syncthreads();
    int excl = inc - s + ((wid > 0) ? wsum[wid - 1] : 0);
    for (int i = 0; i < E; i++) bstart[t * E + i] = excl + loc[i];
    if (t == 1023) bstart[n] = wsum[31];
}

__global__ void k_scan2() {
    if (blockIdx.x == 0) scan_hist(g_cnt1, g_bstart1, NBUK1, NBUK1 / 1024);
    else                 scan_hist(g_cnt2, g_bstart2, NBUK2, NBUK2 / 1024);
}

// ---------------- K3: round-1 in-bucket rank sort -> A1 ----------------
__global__ void k_bsort1() {
    __shared__ unsigned long long sb[8 * CAP1];
    int wid = threadIdx.x >> 5, lane = threadIdx.x & 31;
    int buk = blockIdx.x * 8 + wid;
    int m = g_cnt1[buk]; if (m > CAP1) m = CAP1;
    int start = g_bstart1[buk];
    for (int e = lane; e < m; e += 32) sb[wid * CAP1 + e] = g_pad1[buk * CAP1 + e];
    __syncwarp();
    for (int e = lane; e < m; e += 32) {
        unsigned long long ke = sb[wid * CAP1 + e];
        int r = 0;
        for (int i = 0; i < m; i++) r += (sb[wid * CAP1 + i] < ke) ? 1 : 0;
        g_A1[start + r] = (uint32_t)(ke & 0x7FFFFu);
    }
}

// ---------------- K4: round-2 in-bucket rank sort + fused A1 gather ----------------
__global__ void k_bsort2() {
    __shared__ unsigned long long sb[8 * CAP2B];
    int wid = threadIdx.x >> 5, lane = threadIdx.x & 31;
    int buk = blockIdx.x * 8 + wid;
    int m = g_cnt2[buk]; if (m > CAP2B) m = CAP2B;
    int start = g_bstart2[buk];
    for (int e = lane; e < m; e += 32) sb[wid * CAP2B + e] = g_pad2[buk * CAP2B + e];
    __syncwarp();
    for (int e = lane; e < m; e += 32) {
        unsigned long long ke = sb[wid * CAP2B + e];
        int r = 0;
        for (int i = 0; i < m; i++) r += (sb[wid * CAP2B + i] < ke) ? 1 : 0;
        g_permPre[start + r] = g_A1[(uint32_t)(ke & 0x7FFFFu)];
    }
}

// ---------------- K5: validity bitmask + fused valid_number ----------------
__global__ void k_bitmask(const float* __restrict__ depth) {
    __shared__ int sc;
    if (threadIdx.x == 0) sc = 0;
    __syncthreads();
    int b = blockIdx.y;
    int base = blockIdx.x * 2048;
    int lane = threadIdx.x & 31;
    const float* dp = depth + (size_t)b * HWW;
    int mycnt = 0;
#pragma unroll
    for (int it = 0; it < 8; it++) {
        int p = base + it * 256 + threadIdx.x;
        float d = dp[p];
        unsigned bal = __ballot_sync(0xffffffffu, d < MAXD);
        if (lane == 0) { g_bm[b * NWORDS + (p >> 5)] = bal; mycnt += __popc(bal); }
    }
    if (lane == 0) atomicAdd(&sc, mycnt);
    __syncthreads();
    if (threadIdx.x == 0) atomicAdd(&g_validNum[b], sc);
}

// ---------------- K6: stable compaction, 3-phase (count / scan / write) ----------------
// 1 CTA per batch; thread t owns contiguous positions [t*64, t*64+64) -> stability.
__global__ void k_compact() {
    __shared__ uint32_t bm[NWORDS];   // 40 KB
    __shared__ int wsum[32];
    int b = blockIdx.x, tid = threadIdx.x;
    int lane = tid & 31, wid = tid >> 5;
    for (int i = tid; i < NWORDS; i += 1024) bm[i] = g_bm[b * NWORDS + i];
    __syncthreads();
    int totS = g_bstart2[NBUK2]; if (totS > CAP2T) totS = CAP2T;
    int base = tid * 64;
    int lim = totS - base; if (lim > 64) lim = 64; if (lim < 0) lim = 0;
    uint32_t flags0 = 0, flags1 = 0;
    int cnt = 0;
    for (int k = 0; k < lim; k++) {
        uint32_t p = g_permPre[base + k];
        uint32_t v = (bm[p >> 5] >> (p & 31)) & 1u;
        if (k < 32) flags0 |= v << k; else flags1 |= v << (k - 32);
        cnt += (int)v;
    }
    int inc = cnt;
    for (int o = 1; o < 32; o <<= 1) {
        int u = __shfl_up_sync(0xffffffffu, inc, o);
        if (lane >= o) inc += u;
    }
    if (lane == 31) wsum[wid] = inc;
    __syncthreads();
    if (wid == 0) {
        int v = wsum[lane];
        for (int o = 1; o < 32; o <<= 1) {
            int u = __shfl_up_sync(0xffffffffu, v, o);
            if (lane >= o) v += u;
        }
        wsum[lane] = v;
    }
    __syncthreads();
    int g = inc - cnt + ((wid > 0) ? wsum[wid - 1] : 0);
    if (g >= NN || cnt == 0) return;
    for (int k = 0; k < lim && g < NN; k++) {
        uint32_t v = (k < 32) ? ((flags0 >> k) & 1u) : ((flags1 >> (k - 32)) & 1u);
        if (v) {
            g_validPix[b * NN + g] = (int)g_permPre[base + k];
            g++;
        }
    }
}

// ---------------- K7: epilogue ----------------
__global__ void k_output(const float* __restrict__ depth, const float* __restrict__ invK,
                         const float* __restrict__ bind, float* __restrict__ out) {
    int b = blockIdx.y;
    int n = blockIdx.x * 256 + threadIdx.x;
    float bv = bind[b * NN + n];
    float vnf = (float)g_validNum[b];
    int li = (vnf > 0.0f) ? (int)fmodf(bv, vnf) : 0;
    int p = g_validPix[b * NN + li];
    float d = __ldg(&depth[(size_t)b * HWW + p]);
    float xf = (float)(p & (WW - 1));
    float yf = (float)(p >> 10);
    float px = xf * d, py = yf * d;
    const float* Km = invK + b * 16;
#pragma unroll
    for (int c = 0; c < 3; c++) {
        float v = fmaf(__ldg(&Km[c * 4 + 0]), px,
                  fmaf(__ldg(&Km[c * 4 + 1]), py,
                  fmaf(__ldg(&Km[c * 4 + 2]), d, __ldg(&Km[c * 4 + 3]))));
        out[((size_t)b * 3 + c) * NN + n] = v;
    }
}

// ================================= launch =================================
extern "C" void kernel_launch(void* const* d_in, const int* in_sizes, int n_in,
                              void* d_out, int out_size) {
    const float* depth = (const float*)d_in[0];
    const float* invK  = (const float*)d_in[1];
    const float* bind  = (const float*)d_in[3];
    float* out = (float*)d_out;

    // jax key schedule: key(42) = (0,42); per shuffle round: key,subkey = split(key)
    uint32_t k0 = 0u, k1 = 42u;
    uint32_t sk[2][2];
    for (int r = 0; r < 2; r++) {
        uint32_t nk0, nk1, s0, s1;
        tf2x32(k0, k1, 0u, 0u, nk0, nk1);
        tf2x32(k0, k1, 0u, 1u, s0, s1);
        k0 = nk0; k1 = nk1;
        sk[r][0] = s0; sk[r][1] = s1;
    }

    k_zero   <<<NBUK1 / 256, 256>>>();
    k_prep   <<<HWW / 512, 256>>>(sk[0][0], sk[0][1], sk[1][0], sk[1][1]);
    k_scan2  <<<2, 1024>>>();
    k_bsort1 <<<NBUK1 / 8, 256>>>();
    k_bsort2 <<<NBUK2 / 8, 256>>>();
    k_bitmask<<<dim3(160, BB), 256>>>(depth);
    k_compact<<<BB, 1024>>>();
    k_output <<<dim3(NN / 256, BB), 256>>>(depth, invK, bind, out);
}